// round 4
// baseline (speedup 1.0000x reference)
#include <cuda_runtime.h>

// GlobalContextAttention — fused, occupancy-tuned.
// x (J, F, C=128) fp32, batch_index (F,) int32 SORTED, weight (C,C) fp32 -> out (J, B, C).
//
// Kernel A: precompute segment bounds seg[0..B] (one binary search per segment).
// Kernel B: grid (B, J), 256 thr, 6 CTAs/SM target (75% occ).
//   pass1 segment sum -> mean; gemv gc = tanh(mean @ W); pass2 gated segment mean.
// Pass2 re-reads the ~153KB slice pass1 just streamed -> L2 hit (per-wave footprint
// ~90MB < 126MB L2), so DRAM sees x approximately once.

static constexpr int C_DIM   = 128;
static constexpr int THREADS = 256;
static constexpr int WARPS   = 8;
static constexpr int MAX_SEG = 4096;

__device__ int g_seg[MAX_SEG + 1];

__global__ void seg_bounds_kernel(const int* __restrict__ idx, int Fn, int Bn)
{
    const int t = blockIdx.x * blockDim.x + threadIdx.x;
    if (t > Bn) return;
    int lo = 0, hi = Fn;
    while (lo < hi) {
        int m = (lo + hi) >> 1;
        if (idx[m] < t) lo = m + 1; else hi = m;
    }
    g_seg[t] = lo;
}

__global__ __launch_bounds__(THREADS, 6)
void gca_fused_kernel(const float* __restrict__ x,
                      const float* __restrict__ W,
                      float*       __restrict__ out,
                      int Jn, int Fn, int Bn)
{
    __shared__ float s_red[WARPS][C_DIM];   // 4 KB
    __shared__ float s_vec[C_DIM];          // mean, then gc

    const int tid  = threadIdx.x;
    const int warp = tid >> 5;
    const int lane = tid & 31;
    const int b    = blockIdx.x;
    const int j    = blockIdx.y;

    const int start = g_seg[b];
    const int end   = g_seg[b + 1];
    const int cnt   = end - start;
    const float inv_cnt = 1.0f / (float)(cnt > 0 ? cnt : 1);
    const int ch = lane * 4;                 // this lane's float4 channel group
    const float* xj = x + (size_t)j * Fn * C_DIM;

    // ---------------- pass 1: per-channel segment sum ----------------
    float4 acc = make_float4(0.f, 0.f, 0.f, 0.f);
    int f = start + warp;
    for (; f + 5 * WARPS < end; f += 6 * WARPS) {
#pragma unroll
        for (int u = 0; u < 6; u++) {
            const float4 a = *(const float4*)(xj + (size_t)(f + u * WARPS) * C_DIM + ch);
            acc.x += a.x; acc.y += a.y; acc.z += a.z; acc.w += a.w;
        }
    }
    for (; f < end; f += WARPS) {
        const float4 a = *(const float4*)(xj + (size_t)f * C_DIM + ch);
        acc.x += a.x; acc.y += a.y; acc.z += a.z; acc.w += a.w;
    }
    *(float4*)&s_red[warp][ch] = acc;
    __syncthreads();
    if (tid < C_DIM) {
        float s = 0.f;
#pragma unroll
        for (int w = 0; w < WARPS; w++) s += s_red[w][tid];
        s_vec[tid] = s * inv_cnt;            // mean[j,b,:]
    }
    __syncthreads();

    // ---------------- GEMV: gc = tanh(mean @ W) ----------------
    {
        const int t_out = tid & (C_DIM - 1);
        const int half  = tid >> 7;          // 0..1
        const float* wp = W + (size_t)(half * 64) * C_DIM + t_out;
        float p = 0.f;
#pragma unroll 8
        for (int k = 0; k < 64; k++)
            p += s_vec[half * 64 + k] * wp[(size_t)k * C_DIM];
        s_red[half][t_out] = p;
    }
    __syncthreads();
    if (tid < C_DIM)
        s_vec[tid] = tanhf(s_red[0][tid] + s_red[1][tid]);
    __syncthreads();

    // ---------------- pass 2: gate + gated segment mean ----------------
    const float4 gc4 = *(const float4*)&s_vec[ch];
    float4 oacc = make_float4(0.f, 0.f, 0.f, 0.f);
    f = start + warp;
    for (; f + 2 * WARPS < end; f += 3 * WARPS) {
        const float4 a0 = *(const float4*)(xj + (size_t)(f            ) * C_DIM + ch);
        const float4 a1 = *(const float4*)(xj + (size_t)(f + 1 * WARPS) * C_DIM + ch);
        const float4 a2 = *(const float4*)(xj + (size_t)(f + 2 * WARPS) * C_DIM + ch);
        float d0 = a0.x*gc4.x + a0.y*gc4.y + a0.z*gc4.z + a0.w*gc4.w;
        float d1 = a1.x*gc4.x + a1.y*gc4.y + a1.z*gc4.z + a1.w*gc4.w;
        float d2 = a2.x*gc4.x + a2.y*gc4.y + a2.z*gc4.z + a2.w*gc4.w;
#pragma unroll
        for (int s = 16; s > 0; s >>= 1) {
            d0 += __shfl_xor_sync(0xffffffffu, d0, s);
            d1 += __shfl_xor_sync(0xffffffffu, d1, s);
            d2 += __shfl_xor_sync(0xffffffffu, d2, s);
        }
        const float g0 = 1.f / (1.f + __expf(-d0));
        const float g1 = 1.f / (1.f + __expf(-d1));
        const float g2 = 1.f / (1.f + __expf(-d2));
        oacc.x += g0*a0.x; oacc.y += g0*a0.y; oacc.z += g0*a0.z; oacc.w += g0*a0.w;
        oacc.x += g1*a1.x; oacc.y += g1*a1.y; oacc.z += g1*a1.z; oacc.w += g1*a1.w;
        oacc.x += g2*a2.x; oacc.y += g2*a2.y; oacc.z += g2*a2.z; oacc.w += g2*a2.w;
    }
    for (; f < end; f += WARPS) {
        const float4 a = *(const float4*)(xj + (size_t)f * C_DIM + ch);
        float d = a.x*gc4.x + a.y*gc4.y + a.z*gc4.z + a.w*gc4.w;
#pragma unroll
        for (int s = 16; s > 0; s >>= 1)
            d += __shfl_xor_sync(0xffffffffu, d, s);
        const float g = 1.f / (1.f + __expf(-d));
        oacc.x += g*a.x; oacc.y += g*a.y; oacc.z += g*a.z; oacc.w += g*a.w;
    }
    *(float4*)&s_red[warp][ch] = oacc;
    __syncthreads();
    if (tid < C_DIM) {
        float s = 0.f;
#pragma unroll
        for (int w = 0; w < WARPS; w++) s += s_red[w][tid];
        out[((size_t)j * Bn + b) * C_DIM + tid] = s * inv_cnt;
    }
}

extern "C" void kernel_launch(void* const* d_in, const int* in_sizes, int n_in,
                              void* d_out, int out_size)
{
    // Identify inputs by element count: x = largest; weight = C*C; idx = other multi-element.
    int xi = 0;
    for (int i = 1; i < n_in; i++)
        if (in_sizes[i] > in_sizes[xi]) xi = i;
    int wi = -1, ii = -1;
    for (int i = 0; i < n_in; i++) {
        if (i == xi) continue;
        if (in_sizes[i] == C_DIM * C_DIM && wi < 0) { wi = i; continue; }
        if (in_sizes[i] > 1 && ii < 0) ii = i;
    }
    if (wi < 0 || ii < 0) return;

    const float* x   = (const float*)d_in[xi];
    const int*   idx = (const int*)  d_in[ii];
    const float* W   = (const float*)d_in[wi];
    float*       out = (float*)d_out;

    const int Fn = in_sizes[ii];
    const int Jn = in_sizes[xi] / (Fn * C_DIM);
    int Bn = out_size / (Jn * C_DIM);
    if (Bn > MAX_SEG) Bn = MAX_SEG;

    seg_bounds_kernel<<<(Bn + THREADS) / THREADS + 1, THREADS>>>(idx, Fn, Bn);
    dim3 grid(Bn, Jn);
    gca_fused_kernel<<<grid, THREADS>>>(x, W, out, Jn, Fn, Bn);
}

// round 5
// speedup vs baseline: 1.1625x; 1.1625x over previous
#include <cuda_runtime.h>

// GlobalContextAttention — fused, L2-reuse-pinned.
// x (J, F, C=128) fp32, batch_index (F,) int32 SORTED, weight (C,C) fp32 -> out (J, B, C).
//
// Lesson from R4: occupancy 6 CTAs/SM overflows L2 (136MB of live slices > 126MB)
// and doubles DRAM traffic. So we PIN occupancy at 4 CTAs/SM via a 42KB smem pad
// (90MB live slices -> pass2 hits L2, x read from DRAM ~once), and instead buy
// latency hiding with deeper per-warp unroll (pass1 x8, pass2 x6 interleaved).

static constexpr int C_DIM   = 128;
static constexpr int THREADS = 256;
static constexpr int WARPS   = 8;
static constexpr int MAX_SEG = 4096;

__device__ int g_seg[MAX_SEG + 1];

__global__ void seg_bounds_kernel(const int* __restrict__ idx, int Fn, int Bn)
{
    const int t = blockIdx.x * blockDim.x + threadIdx.x;
    if (t > Bn) return;
    int lo = 0, hi = Fn;
    while (lo < hi) {
        int m = (lo + hi) >> 1;
        if (idx[m] < t) lo = m + 1; else hi = m;
    }
    g_seg[t] = lo;
}

__global__ __launch_bounds__(THREADS, 4)
void gca_fused_kernel(const float* __restrict__ x,
                      const float* __restrict__ W,
                      float*       __restrict__ out,
                      int Jn, int Fn, int Bn)
{
    __shared__ float s_red[WARPS][C_DIM];     // 4 KB working reduction buffer
    __shared__ float s_vec[C_DIM];            // mean, then gc (0.5 KB)
    __shared__ float s_pad[10624];            // 41.5 KB pad -> 46 KB total -> 4 CTAs/SM max

    const int tid  = threadIdx.x;
    const int warp = tid >> 5;
    const int lane = tid & 31;
    const int b    = blockIdx.x;
    const int j    = blockIdx.y;

    // Keep the pad alive without doing work (never true at runtime: Jn > 0).
    if (Jn < 0) s_pad[tid] = 0.f, out[tid] = s_pad[tid + 1];

    const int start = g_seg[b];
    const int end   = g_seg[b + 1];
    const int cnt   = end - start;
    const float inv_cnt = 1.0f / (float)(cnt > 0 ? cnt : 1);
    const int ch = lane * 4;                  // this lane's float4 channel group
    const float* xj = x + (size_t)j * Fn * C_DIM;

    // ---------------- pass 1: per-channel segment sum ----------------
    float4 acc = make_float4(0.f, 0.f, 0.f, 0.f);
    int f = start + warp;
    for (; f + 7 * WARPS < end; f += 8 * WARPS) {
#pragma unroll
        for (int u = 0; u < 8; u++) {
            const float4 a = *(const float4*)(xj + (size_t)(f + u * WARPS) * C_DIM + ch);
            acc.x += a.x; acc.y += a.y; acc.z += a.z; acc.w += a.w;
        }
    }
    for (; f < end; f += WARPS) {
        const float4 a = *(const float4*)(xj + (size_t)f * C_DIM + ch);
        acc.x += a.x; acc.y += a.y; acc.z += a.z; acc.w += a.w;
    }
    *(float4*)&s_red[warp][ch] = acc;
    __syncthreads();
    if (tid < C_DIM) {
        float s = 0.f;
#pragma unroll
        for (int w = 0; w < WARPS; w++) s += s_red[w][tid];
        s_vec[tid] = s * inv_cnt;             // mean[j,b,:]
    }
    __syncthreads();

    // ---------------- GEMV: gc = tanh(mean @ W) ----------------
    {
        const int t_out = tid & (C_DIM - 1);
        const int half  = tid >> 7;           // 0..1
        const float* wp = W + (size_t)(half * 64) * C_DIM + t_out;
        float p = 0.f;
#pragma unroll 8
        for (int k = 0; k < 64; k++)
            p += s_vec[half * 64 + k] * wp[(size_t)k * C_DIM];
        s_red[half][t_out] = p;
    }
    __syncthreads();
    if (tid < C_DIM)
        s_vec[tid] = tanhf(s_red[0][tid] + s_red[1][tid]);
    __syncthreads();

    // ---------------- pass 2: gate + gated segment mean (unroll 6) ----------------
    const float4 gc4 = *(const float4*)&s_vec[ch];
    float4 oacc = make_float4(0.f, 0.f, 0.f, 0.f);
    f = start + warp;
    for (; f + 5 * WARPS < end; f += 6 * WARPS) {
        float4 a[6];
#pragma unroll
        for (int u = 0; u < 6; u++)
            a[u] = *(const float4*)(xj + (size_t)(f + u * WARPS) * C_DIM + ch);
        float d[6];
#pragma unroll
        for (int u = 0; u < 6; u++)
            d[u] = a[u].x*gc4.x + a[u].y*gc4.y + a[u].z*gc4.z + a[u].w*gc4.w;
#pragma unroll
        for (int s = 16; s > 0; s >>= 1) {
#pragma unroll
            for (int u = 0; u < 6; u++)
                d[u] += __shfl_xor_sync(0xffffffffu, d[u], s);
        }
#pragma unroll
        for (int u = 0; u < 6; u++) {
            const float g = 1.f / (1.f + __expf(-d[u]));
            oacc.x += g*a[u].x; oacc.y += g*a[u].y; oacc.z += g*a[u].z; oacc.w += g*a[u].w;
        }
    }
    for (; f < end; f += WARPS) {
        const float4 a = *(const float4*)(xj + (size_t)f * C_DIM + ch);
        float d = a.x*gc4.x + a.y*gc4.y + a.z*gc4.z + a.w*gc4.w;
#pragma unroll
        for (int s = 16; s > 0; s >>= 1)
            d += __shfl_xor_sync(0xffffffffu, d, s);
        const float g = 1.f / (1.f + __expf(-d));
        oacc.x += g*a.x; oacc.y += g*a.y; oacc.z += g*a.z; oacc.w += g*a.w;
    }
    *(float4*)&s_red[warp][ch] = oacc;
    __syncthreads();
    if (tid < C_DIM) {
        float s = 0.f;
#pragma unroll
        for (int w = 0; w < WARPS; w++) s += s_red[w][tid];
        out[((size_t)j * Bn + b) * C_DIM + tid] = s * inv_cnt;
    }
}

extern "C" void kernel_launch(void* const* d_in, const int* in_sizes, int n_in,
                              void* d_out, int out_size)
{
    // Identify inputs by element count: x = largest; weight = C*C; idx = other multi-element.
    int xi = 0;
    for (int i = 1; i < n_in; i++)
        if (in_sizes[i] > in_sizes[xi]) xi = i;
    int wi = -1, ii = -1;
    for (int i = 0; i < n_in; i++) {
        if (i == xi) continue;
        if (in_sizes[i] == C_DIM * C_DIM && wi < 0) { wi = i; continue; }
        if (in_sizes[i] > 1 && ii < 0) ii = i;
    }
    if (wi < 0 || ii < 0) return;

    const float* x   = (const float*)d_in[xi];
    const int*   idx = (const int*)  d_in[ii];
    const float* W   = (const float*)d_in[wi];
    float*       out = (float*)d_out;

    const int Fn = in_sizes[ii];
    const int Jn = in_sizes[xi] / (Fn * C_DIM);
    int Bn = out_size / (Jn * C_DIM);
    if (Bn > MAX_SEG) Bn = MAX_SEG;

    seg_bounds_kernel<<<(Bn + THREADS) / THREADS + 1, THREADS>>>(idx, Fn, Bn);
    dim3 grid(Bn, Jn);
    gca_fused_kernel<<<grid, THREADS>>>(x, W, out, Jn, Fn, Bn);
}